// round 4
// baseline (speedup 1.0000x reference)
#include <cuda_runtime.h>
#include <cuda_fp16.h>
#include <cstdint>

// ============================================================================
// Efficient_SKAN_Base as ONE fused GEMM: out[b,o] = sum_k A[b,k]*W[k,o] + bias[o]
//   A[b, 0:128]       = silu(x[b,:])
//   A[b, 128j : +128] = sin(grid[j-1] * x[b,:])   j=1..8
// Engine: mma.sync m16n8k16 fp16->fp32, ldmatrix, x in registers, feature-gen
// interleaved into the MMA k-loop. R4: 2 CTAs/SM (128 thr, M=64 tile) so the
// per-chunk barrier/latency bubbles of one CTA hide under the other.
// ============================================================================

#define B_ROWS   131072
#define NUM_F    8
#define NCHUNK   9
#define ROW_H    136              // halves per K-row (128 + 8 pad)
#define ROW_B    (ROW_H * 2)      // 272 B (17 x 16B -> conflict-free LDSM/STS)
#define B_CHUNK  (128 * ROW_B)    // 34816: 128x128 fp16 weight tile
#define A_CHUNK  (64 * ROW_B)     // 17408: 64x128 fp16 feature tile

__device__ __half g_W[NCHUNK * 128 * ROW_H];
__device__ float  g_bias[128];

// smem: A0 A1 (64-row) + B0 B1 (128-row), double-buffered
#define S_A0 0
#define S_A1 A_CHUNK
#define S_B0 (2 * A_CHUNK)
#define S_B1 (2 * A_CHUNK + B_CHUNK)
#define S_TOTAL (2 * A_CHUNK + 2 * B_CHUNK)   // 104448 B -> 2 CTA/SM

// ---------------- helpers ----------------
static __device__ __forceinline__ uint32_t smem_u32(const void* p) {
    uint32_t a;
    asm("{ .reg .u64 t; cvta.to.shared.u64 t, %1; cvt.u32.u64 %0, t; }" : "=r"(a) : "l"(p));
    return a;
}
static __device__ __forceinline__ void cp16(uint32_t s, const void* g) {
    asm volatile("cp.async.cg.shared.global [%0], [%1], 16;" :: "r"(s), "l"(g));
}
static __device__ __forceinline__ void cp_commit() {
    asm volatile("cp.async.commit_group;" ::: "memory");
}
static __device__ __forceinline__ void cp_wait_all() {
    asm volatile("cp.async.wait_group 0;" ::: "memory");
}
static __device__ __forceinline__ uint32_t h2u(__half2 h) {
    return *reinterpret_cast<uint32_t*>(&h);
}
static __device__ __forceinline__ void ldsm4(uint32_t* r, uint32_t addr) {
    asm volatile("ldmatrix.sync.aligned.m8n8.x4.shared.b16 {%0,%1,%2,%3}, [%4];"
                 : "=r"(r[0]), "=r"(r[1]), "=r"(r[2]), "=r"(r[3]) : "r"(addr));
}
static __device__ __forceinline__ void hmma(float* d, const uint32_t* a,
                                            uint32_t b0, uint32_t b1) {
    asm volatile("mma.sync.aligned.m16n8k16.row.col.f32.f16.f16.f32 "
                 "{%0,%1,%2,%3},{%4,%5,%6,%7},{%8,%9},{%0,%1,%2,%3};"
                 : "+f"(d[0]), "+f"(d[1]), "+f"(d[2]), "+f"(d[3])
                 : "r"(a[0]), "r"(a[1]), "r"(a[2]), "r"(a[3]), "r"(b0), "r"(b1));
}

// ============================================================================
// Prep: fold coef & scale_sp into weights, fp16, padded layout.
// ============================================================================
__global__ void skan_prep(const float* __restrict__ base_w,
                          const float* __restrict__ scale_sp,
                          const float* __restrict__ coef,
                          const float* __restrict__ conv_w,
                          const float* __restrict__ conv_b) {
    int idx = blockIdx.x * 256 + threadIdx.x;
    const int total = NCHUNK * 128 * ROW_H;
    if (idx < total) {
        int c  = idx / (128 * ROW_H);
        int r  = idx % (128 * ROW_H);
        int n  = r / ROW_H;
        int kq = r % ROW_H;
        float v = 0.f;
        if (kq < 128) {
            if (c == 0) v = base_w[n * 128 + kq];
            else {
                int f = c - 1;
                v = conv_w[f * 16384 + n * 128 + kq] * coef[kq * NUM_F + f] * scale_sp[n];
            }
        }
        g_W[idx] = __float2half_rn(v);
    }
    if (idx < 128) {
        float s = 0.f;
        #pragma unroll
        for (int f = 0; f < NUM_F; f++) s += conv_b[f * 128 + idx];
        g_bias[idx] = s * scale_sp[idx];
    }
}

// cp.async one pre-folded weight chunk into smem (128 threads)
static __device__ __forceinline__ void ldB(uint32_t bbuf, int c, int tid) {
    const char* src = reinterpret_cast<const char*>(g_W) + (size_t)c * B_CHUNK;
    #pragma unroll
    for (int i = tid; i < B_CHUNK / 16; i += 128)
        cp16(bbuf + i * 16, src + (size_t)i * 16);
}

// ============================================================================
__global__ __launch_bounds__(128, 2) void skan_main(const float* __restrict__ x,
                                                    const float* __restrict__ grid,
                                                    float* __restrict__ out) {
    extern __shared__ char smem[];
    const int tid = threadIdx.x;
    const int lane = tid & 31, wid = tid >> 5;
    const size_t m0 = (size_t)blockIdx.x * 64;
    const uint32_t sb = smem_u32(smem);

    // genA ownership: row = tid&63 (of 64-row tile), half kh = tid>>6
    const int grow = tid & 63;
    const int kh = tid >> 6;

    // x in registers: the 64 values this thread converts each chunk
    float4 xv[16];
    {
        const float4* xg = reinterpret_cast<const float4*>(x + (m0 + grow) * 128 + kh * 64);
        #pragma unroll
        for (int j = 0; j < 16; j++) xv[j] = xg[j];
    }

    // prefetch weight chunk 0
    ldB(sb + S_B0, 0, tid);
    cp_commit();

    // generate chunk 0 (silu) into A0
    {
        char* arow = smem + S_A0 + grow * ROW_B + kh * 128;
        #pragma unroll
        for (int ks = 0; ks < 8; ks++) {
            float4 x0 = xv[2 * ks], x1 = xv[2 * ks + 1];
            float v0 = __fdividef(x0.x, 1.f + __expf(-x0.x));
            float v1 = __fdividef(x0.y, 1.f + __expf(-x0.y));
            float v2 = __fdividef(x0.z, 1.f + __expf(-x0.z));
            float v3 = __fdividef(x0.w, 1.f + __expf(-x0.w));
            float v4 = __fdividef(x1.x, 1.f + __expf(-x1.x));
            float v5 = __fdividef(x1.y, 1.f + __expf(-x1.y));
            float v6 = __fdividef(x1.z, 1.f + __expf(-x1.z));
            float v7 = __fdividef(x1.w, 1.f + __expf(-x1.w));
            uint4 pk;
            pk.x = h2u(__floats2half2_rn(v0, v1));
            pk.y = h2u(__floats2half2_rn(v2, v3));
            pk.z = h2u(__floats2half2_rn(v4, v5));
            pk.w = h2u(__floats2half2_rn(v6, v7));
            *(uint4*)(arow + ks * 16) = pk;
        }
    }

    // warp grid 2x2: wm = wid>>1 (rows wm*32), wn = wid&1 (cols wn*64)
    const int wm = wid >> 1, wn = wid & 1;
    const uint32_t alo = (uint32_t)(wm * 32 + ((lane >> 3) & 1) * 8 + (lane & 7)) * ROW_B
                       + ((lane >> 4) & 1) * 16;
    const uint32_t blo = (uint32_t)(wn * 64 + ((lane >> 4) & 1) * 8 + (lane & 7)) * ROW_B
                       + ((lane >> 3) & 1) * 16;

    float acc[2][8][4];
    #pragma unroll
    for (int mt = 0; mt < 2; mt++)
        #pragma unroll
        for (int nt = 0; nt < 8; nt++)
            #pragma unroll
            for (int v = 0; v < 4; v++) acc[mt][nt][v] = 0.f;

    #pragma unroll 1
    for (int c = 0; c < NCHUNK; c++) {
        cp_wait_all();        // weight chunk c landed
        __syncthreads();      // A(c) visible; prev-chunk buffers free

        const int buf = c & 1;
        const uint32_t abuf = sb + (buf ? S_A1 : S_A0);
        const uint32_t bbuf = sb + (buf ? S_B1 : S_B0);
        char* anext = smem + (buf ? S_A0 : S_A1) + grow * ROW_B + kh * 128;

        const bool gen = (c + 1 < NCHUNK);
        float g = 0.f;
        if (gen) {
            g = __ldg(grid + c);                   // chunk c+1 frequency
            ldB(sb + (buf ? S_B0 : S_B1), c + 1, tid);
            cp_commit();
        }

        #pragma unroll
        for (int ks = 0; ks < 8; ks++) {
            uint32_t a0r[4], a1r[4];
            ldsm4(a0r, abuf + alo + ks * 32);
            ldsm4(a1r, abuf + alo + 16 * ROW_B + ks * 32);
            #pragma unroll
            for (int m = 0; m < 4; m++) {
                uint32_t br[4];
                ldsm4(br, bbuf + blo + (uint32_t)m * 16 * ROW_B + ks * 32);
                hmma(acc[0][2 * m],     a0r, br[0], br[1]);
                hmma(acc[0][2 * m + 1], a0r, br[2], br[3]);
                hmma(acc[1][2 * m],     a1r, br[0], br[1]);
                hmma(acc[1][2 * m + 1], a1r, br[2], br[3]);
            }
            if (gen) {   // one slice of sin-feature gen for chunk c+1
                float4 x0 = xv[2 * ks], x1 = xv[2 * ks + 1];
                uint4 pk;
                pk.x = h2u(__floats2half2_rn(__sinf(g * x0.x), __sinf(g * x0.y)));
                pk.y = h2u(__floats2half2_rn(__sinf(g * x0.z), __sinf(g * x0.w)));
                pk.z = h2u(__floats2half2_rn(__sinf(g * x1.x), __sinf(g * x1.y)));
                pk.w = h2u(__floats2half2_rn(__sinf(g * x1.z), __sinf(g * x1.w)));
                *(uint4*)(anext + ks * 16) = pk;
            }
        }
    }

    // epilogue: + bias, float2 stores
    {
        const int l4 = lane >> 2, q = lane & 3;
        #pragma unroll
        for (int nt = 0; nt < 8; nt++) {
            const int col = wn * 64 + nt * 8 + q * 2;
            const float bx = __ldg(g_bias + col);
            const float by = __ldg(g_bias + col + 1);
            #pragma unroll
            for (int mt = 0; mt < 2; mt++) {
                const size_t r = m0 + wm * 32 + mt * 16 + l4;
                float2 v0 = make_float2(acc[mt][nt][0] + bx, acc[mt][nt][1] + by);
                float2 v1 = make_float2(acc[mt][nt][2] + bx, acc[mt][nt][3] + by);
                *(float2*)(out + r * 128 + col)       = v0;
                *(float2*)(out + (r + 8) * 128 + col) = v1;
            }
        }
    }
}

// ============================================================================
extern "C" void kernel_launch(void* const* d_in, const int* in_sizes, int n_in,
                              void* d_out, int out_size) {
    (void)in_sizes; (void)n_in; (void)out_size;
    const float* x        = (const float*)d_in[0];
    const float* grid     = (const float*)d_in[1];
    const float* base_w   = (const float*)d_in[2];
    const float* scale_sp = (const float*)d_in[3];
    const float* coef     = (const float*)d_in[4];
    const float* conv_w   = (const float*)d_in[5];
    const float* conv_b   = (const float*)d_in[6];
    float* out = (float*)d_out;

    cudaFuncSetAttribute(skan_main, cudaFuncAttributeMaxDynamicSharedMemorySize, S_TOTAL);

    const int prep_total = NCHUNK * 128 * ROW_H;
    skan_prep<<<(prep_total + 255) / 256, 256>>>(base_w, scale_sp, coef, conv_w, conv_b);
    skan_main<<<B_ROWS / 64, 128, S_TOTAL>>>(x, grid, out);
}

// round 5
// speedup vs baseline: 1.1267x; 1.1267x over previous
#include <cuda_runtime.h>
#include <cuda_fp16.h>
#include <cstdint>

// ============================================================================
// Efficient_SKAN_Base as ONE fused GEMM: out[b,o] = sum_k A[b,k]*W[k,o] + bias[o]
//   A[b, 0:128]       = silu(x[b,:])
//   A[b, 128j : +128] = sin(grid[j-1] * x[b,:])   j=1..8
// R5: warp-specialized. 512 threads: warps 0-7 = consumers (pure LDSM+HMMA),
// warps 8-15 = producers (feature gen + weight cp.async). One sync per chunk.
// ============================================================================

#define B_ROWS   131072
#define NUM_F    8
#define NCHUNK   9
#define ROW_H    136              // halves per K-row (128 + 8 pad)
#define ROW_B    (ROW_H * 2)      // 272 B -> conflict-free LDSM/STS
#define CHUNK_BYTES (128 * ROW_B) // 34816 per 128x128 fp16 tile

__device__ __half g_W[NCHUNK * 128 * ROW_H];
__device__ float  g_bias[128];

#define S_A0 0
#define S_A1 CHUNK_BYTES
#define S_B0 (2 * CHUNK_BYTES)
#define S_B1 (3 * CHUNK_BYTES)
#define S_TOTAL (4 * CHUNK_BYTES)   // 139264 B -> 1 CTA/SM (512 thr)

// ---------------- helpers ----------------
static __device__ __forceinline__ uint32_t smem_u32(const void* p) {
    uint32_t a;
    asm("{ .reg .u64 t; cvta.to.shared.u64 t, %1; cvt.u32.u64 %0, t; }" : "=r"(a) : "l"(p));
    return a;
}
static __device__ __forceinline__ void cp16(uint32_t s, const void* g) {
    asm volatile("cp.async.cg.shared.global [%0], [%1], 16;" :: "r"(s), "l"(g));
}
static __device__ __forceinline__ void cp_commit() {
    asm volatile("cp.async.commit_group;" ::: "memory");
}
static __device__ __forceinline__ void cp_wait_all() {
    asm volatile("cp.async.wait_group 0;" ::: "memory");
}
static __device__ __forceinline__ uint32_t h2u(__half2 h) {
    return *reinterpret_cast<uint32_t*>(&h);
}
static __device__ __forceinline__ void ldsm4(uint32_t* r, uint32_t addr) {
    asm volatile("ldmatrix.sync.aligned.m8n8.x4.shared.b16 {%0,%1,%2,%3}, [%4];"
                 : "=r"(r[0]), "=r"(r[1]), "=r"(r[2]), "=r"(r[3]) : "r"(addr));
}
static __device__ __forceinline__ void hmma(float* d, const uint32_t* a,
                                            uint32_t b0, uint32_t b1) {
    asm volatile("mma.sync.aligned.m16n8k16.row.col.f32.f16.f16.f32 "
                 "{%0,%1,%2,%3},{%4,%5,%6,%7},{%8,%9},{%0,%1,%2,%3};"
                 : "+f"(d[0]), "+f"(d[1]), "+f"(d[2]), "+f"(d[3])
                 : "r"(a[0]), "r"(a[1]), "r"(a[2]), "r"(a[3]), "r"(b0), "r"(b1));
}

// ============================================================================
// Prep: fold coef & scale_sp into weights, fp16, padded layout.
// ============================================================================
__global__ void skan_prep(const float* __restrict__ base_w,
                          const float* __restrict__ scale_sp,
                          const float* __restrict__ coef,
                          const float* __restrict__ conv_w,
                          const float* __restrict__ conv_b) {
    int idx = blockIdx.x * 256 + threadIdx.x;
    const int total = NCHUNK * 128 * ROW_H;
    if (idx < total) {
        int c  = idx / (128 * ROW_H);
        int r  = idx % (128 * ROW_H);
        int n  = r / ROW_H;
        int kq = r % ROW_H;
        float v = 0.f;
        if (kq < 128) {
            if (c == 0) v = base_w[n * 128 + kq];
            else {
                int f = c - 1;
                v = conv_w[f * 16384 + n * 128 + kq] * coef[kq * NUM_F + f] * scale_sp[n];
            }
        }
        g_W[idx] = __float2half_rn(v);
    }
    if (idx < 128) {
        float s = 0.f;
        #pragma unroll
        for (int f = 0; f < NUM_F; f++) s += conv_b[f * 128 + idx];
        g_bias[idx] = s * scale_sp[idx];
    }
}

// cp.async one pre-folded weight chunk (issued by 256 producer threads)
static __device__ __forceinline__ void ldB(uint32_t bbuf, int c, int ptid) {
    const char* src = reinterpret_cast<const char*>(g_W) + (size_t)c * CHUNK_BYTES;
    #pragma unroll
    for (int i = ptid; i < CHUNK_BYTES / 16; i += 256)
        cp16(bbuf + i * 16, src + (size_t)i * 16);
}

// ============================================================================
__global__ __launch_bounds__(512, 1) void skan_main(const float* __restrict__ x,
                                                    const float* __restrict__ grid,
                                                    float* __restrict__ out) {
    extern __shared__ char smem[];
    const int tid = threadIdx.x;
    const int lane = tid & 31, wid = tid >> 5;
    const size_t m0 = (size_t)blockIdx.x * 128;
    const uint32_t sb = smem_u32(smem);
    const bool producer = (wid >= 8);

    if (producer) {
        // ---------------- PRODUCER: warps 8-15, 256 threads -----------------
        const int ptid = tid - 256;
        const int grow = ptid & 127;       // A row owned
        const int kh = ptid >> 7;          // k-half (64 cols)

        float4 xv[16];
        {
            const float4* xg =
                reinterpret_cast<const float4*>(x + (m0 + grow) * 128 + kh * 64);
            #pragma unroll
            for (int j = 0; j < 16; j++) xv[j] = xg[j];
        }

        ldB(sb + S_B0, 0, ptid);
        cp_commit();

        // chunk 0: silu into A0
        {
            char* arow = smem + S_A0 + grow * ROW_B + kh * 128;
            #pragma unroll
            for (int ks = 0; ks < 8; ks++) {
                float4 x0 = xv[2 * ks], x1 = xv[2 * ks + 1];
                float v0 = __fdividef(x0.x, 1.f + __expf(-x0.x));
                float v1 = __fdividef(x0.y, 1.f + __expf(-x0.y));
                float v2 = __fdividef(x0.z, 1.f + __expf(-x0.z));
                float v3 = __fdividef(x0.w, 1.f + __expf(-x0.w));
                float v4 = __fdividef(x1.x, 1.f + __expf(-x1.x));
                float v5 = __fdividef(x1.y, 1.f + __expf(-x1.y));
                float v6 = __fdividef(x1.z, 1.f + __expf(-x1.z));
                float v7 = __fdividef(x1.w, 1.f + __expf(-x1.w));
                uint4 pk;
                pk.x = h2u(__floats2half2_rn(v0, v1));
                pk.y = h2u(__floats2half2_rn(v2, v3));
                pk.z = h2u(__floats2half2_rn(v4, v5));
                pk.w = h2u(__floats2half2_rn(v6, v7));
                *(uint4*)(arow + ks * 16) = pk;
            }
        }
        cp_wait_all();
        __syncthreads();    // chunk 0 ready

        #pragma unroll 1
        for (int c = 0; c < NCHUNK; c++) {
            if (c + 1 < NCHUNK) {
                const int nbuf = (c + 1) & 1;
                const float g = __ldg(grid + c);
                ldB(sb + (nbuf ? S_B1 : S_B0), c + 1, ptid);
                cp_commit();
                char* arow = smem + (nbuf ? S_A1 : S_A0) + grow * ROW_B + kh * 128;
                #pragma unroll
                for (int ks = 0; ks < 8; ks++) {
                    float4 x0 = xv[2 * ks], x1 = xv[2 * ks + 1];
                    uint4 pk;
                    pk.x = h2u(__floats2half2_rn(__sinf(g * x0.x), __sinf(g * x0.y)));
                    pk.y = h2u(__floats2half2_rn(__sinf(g * x0.z), __sinf(g * x0.w)));
                    pk.z = h2u(__floats2half2_rn(__sinf(g * x1.x), __sinf(g * x1.y)));
                    pk.w = h2u(__floats2half2_rn(__sinf(g * x1.z), __sinf(g * x1.w)));
                    *(uint4*)(arow + ks * 16) = pk;
                }
                cp_wait_all();
            }
            __syncthreads();   // end-of-chunk barrier (paired with consumer)
        }
        // producers done; consumers write the epilogue
    } else {
        // ---------------- CONSUMER: warps 0-7, pure MMA ---------------------
        const int wm = wid >> 1, wn = wid & 1;   // warp tile 32x64
        const uint32_t alo =
            (uint32_t)(wm * 32 + ((lane >> 3) & 1) * 8 + (lane & 7)) * ROW_B
            + ((lane >> 4) & 1) * 16;
        const uint32_t blo =
            (uint32_t)(wn * 64 + ((lane >> 4) & 1) * 8 + (lane & 7)) * ROW_B
            + ((lane >> 3) & 1) * 16;

        float acc[2][8][4];
        #pragma unroll
        for (int mt = 0; mt < 2; mt++)
            #pragma unroll
            for (int nt = 0; nt < 8; nt++)
                #pragma unroll
                for (int v = 0; v < 4; v++) acc[mt][nt][v] = 0.f;

        __syncthreads();    // wait chunk 0

        #pragma unroll 1
        for (int c = 0; c < NCHUNK; c++) {
            const int buf = c & 1;
            const uint32_t abuf = sb + (buf ? S_A1 : S_A0);
            const uint32_t bbuf = sb + (buf ? S_B1 : S_B0);
            #pragma unroll
            for (int ks = 0; ks < 8; ks++) {
                uint32_t a0r[4], a1r[4];
                ldsm4(a0r, abuf + alo + ks * 32);
                ldsm4(a1r, abuf + alo + 16 * ROW_B + ks * 32);
                #pragma unroll
                for (int m = 0; m < 4; m++) {
                    uint32_t br[4];
                    ldsm4(br, bbuf + blo + (uint32_t)m * 16 * ROW_B + ks * 32);
                    hmma(acc[0][2 * m],     a0r, br[0], br[1]);
                    hmma(acc[0][2 * m + 1], a0r, br[2], br[3]);
                    hmma(acc[1][2 * m],     a1r, br[0], br[1]);
                    hmma(acc[1][2 * m + 1], a1r, br[2], br[3]);
                }
            }
            __syncthreads();   // end-of-chunk barrier (paired with producer)
        }

        // epilogue: + bias, float2 stores
        const int l4 = lane >> 2, q = lane & 3;
        #pragma unroll
        for (int nt = 0; nt < 8; nt++) {
            const int col = wn * 64 + nt * 8 + q * 2;
            const float bx = __ldg(g_bias + col);
            const float by = __ldg(g_bias + col + 1);
            #pragma unroll
            for (int mt = 0; mt < 2; mt++) {
                const size_t r = m0 + wm * 32 + mt * 16 + l4;
                float2 v0 = make_float2(acc[mt][nt][0] + bx, acc[mt][nt][1] + by);
                float2 v1 = make_float2(acc[mt][nt][2] + bx, acc[mt][nt][3] + by);
                *(float2*)(out + r * 128 + col)       = v0;
                *(float2*)(out + (r + 8) * 128 + col) = v1;
            }
        }
    }
}

// ============================================================================
extern "C" void kernel_launch(void* const* d_in, const int* in_sizes, int n_in,
                              void* d_out, int out_size) {
    (void)in_sizes; (void)n_in; (void)out_size;
    const float* x        = (const float*)d_in[0];
    const float* grid     = (const float*)d_in[1];
    const float* base_w   = (const float*)d_in[2];
    const float* scale_sp = (const float*)d_in[3];
    const float* coef     = (const float*)d_in[4];
    const float* conv_w   = (const float*)d_in[5];
    const float* conv_b   = (const float*)d_in[6];
    float* out = (float*)d_out;

    cudaFuncSetAttribute(skan_main, cudaFuncAttributeMaxDynamicSharedMemorySize, S_TOTAL);

    const int prep_total = NCHUNK * 128 * ROW_H;
    skan_prep<<<(prep_total + 255) / 256, 256>>>(base_w, scale_sp, coef, conv_w, conv_b);
    skan_main<<<B_ROWS / 128, 512, S_TOTAL>>>(x, grid, out);
}